// round 1
// baseline (speedup 1.0000x reference)
#include <cuda_runtime.h>
#include <math.h>

#define NN 100000
#define NE 1600000
#define DF 64
#define NTILES (NN / 16)   // 6250 tiles of 16 nodes
#define WS 66              // padded W row stride (floats): conflict-free float2 LDS

// ---------------- device scratch (static: no allocation allowed) ----------------
__device__ float g_U [NN * DF];
__device__ float g_Vf[NN * DF];
__device__ float g_Vt[NN * DF];
__device__ float g_outinv[NN];
__device__ float g_ininv [NN];
__device__ int   g_degout[NN];
__device__ int   g_degin [NN];
__device__ float g_Wr[DF * DF];   // effective Wr, [o][d]
__device__ float g_Wi[DF * DF];   // effective Wi, [o][d]
__device__ float g_breal[DF];     // br_eff - bi_eff
__device__ float g_bimag[DF];     // br_eff + bi_eff

// ---------------- helpers ----------------
__device__ __forceinline__ void ffma2(unsigned long long& acc,
                                      unsigned long long a,
                                      unsigned long long b) {
    // packed f32x2 FMA: full-rate fp32 on sm_103a (scalar FFMA is half-rate)
    asm("fma.rn.f32x2 %0, %1, %2, %0;" : "+l"(acc) : "l"(a), "l"(b));
}

__device__ __forceinline__ float2 unpack2(unsigned long long v) {
    float2 r;
    asm("mov.b64 {%0, %1}, %2;" : "=f"(r.x), "=f"(r.y) : "l"(v));
    return r;
}

// ---------------- kernels ----------------
__global__ void k_zero_deg() {
    int i = blockIdx.x * blockDim.x + threadIdx.x;
    if (i < NN) { g_degout[i] = 0; g_degin[i] = 0; }
}

__global__ void k_deg(const int* __restrict__ ei) {
    int i = blockIdx.x * blockDim.x + threadIdx.x;
    if (i < NE) {
        atomicAdd(&g_degout[ei[i]], 1);
        atomicAdd(&g_degin [ei[NE + i]], 1);
    }
}

__global__ void k_inv() {
    int i = blockIdx.x * blockDim.x + threadIdx.x;
    if (i < NN) {
        int dout = g_degout[i];
        int din  = g_degin[i];
        g_outinv[i] = (dout > 0) ? powf((float)dout, -0.25f) : 0.0f;
        g_ininv [i] = (din  > 0) ? powf((float)din,  -0.25f) : 0.0f;
    }
}

__global__ void k_weights(const float* __restrict__ Wr, const float* __restrict__ br,
                          const float* __restrict__ Wi, const float* __restrict__ bi) {
    int i = blockIdx.x * blockDim.x + threadIdx.x;
    if (i < DF * DF) {
        g_Wr[i] = Wr[i] + 0.5f * Wr[4096 + i] + 0.25f * Wr[8192 + i];
        g_Wi[i] = Wi[i] + 0.5f * Wi[4096 + i] + 0.25f * Wi[8192 + i];
    }
    if (i < DF) {
        float bre = br[i] + 0.5f * br[64 + i] + 0.25f * br[128 + i];
        float bie = bi[i] + 0.5f * bi[64 + i] + 0.25f * bi[128 + i];
        g_breal[i] = bre - bie;
        g_bimag[i] = bre + bie;
    }
}

// Fused dense transform: per node compute
//   a = xr@Wr, b = xi@Wi, q = xi@Wr, r = xr@Wi
//   U = 0.5(a-b), Vt = 0.5q, Vf = r + 0.5q
// 256 threads/block: 16 nodes per tile, 16 threads per node,
// each thread produces 4 outputs (o, o+16, o+32, o+48) via packed f32x2 FMA.
__global__ __launch_bounds__(256) void k_transform(const float* __restrict__ xr,
                                                   const float* __restrict__ xi) {
    __shared__ __align__(16) float sWr[DF * WS];
    __shared__ __align__(16) float sWi[DF * WS];
    __shared__ __align__(16) float sx[16 * 2 * DF]; // per node: 64 xr, 64 xi

    int t = threadIdx.x;
    for (int i = t; i < DF * DF; i += 256) {
        int o = i >> 6, d = i & 63;
        sWr[o * WS + d] = g_Wr[i];
        sWi[o * WS + d] = g_Wi[i];
    }
    __syncthreads();

    int node = t >> 4;     // 0..15
    int oq   = t & 15;     // output quarter index

    for (int tile = blockIdx.x; tile < NTILES; tile += gridDim.x) {
        int nbase = tile * 16;
        // stage x: 16 nodes x 32 float4 (xr then xi)
        for (int i = t; i < 512; i += 256) {
            int nd = i >> 5;
            int k  = i & 31;
            float4 v = (k < 16) ? ((const float4*)xr)[(size_t)(nbase + nd) * 16 + k]
                                : ((const float4*)xi)[(size_t)(nbase + nd) * 16 + (k - 16)];
            ((float4*)sx)[nd * 32 + k] = v;
        }
        __syncthreads();

        unsigned long long accA[4] = {0,0,0,0}, accB[4] = {0,0,0,0};
        unsigned long long accQ[4] = {0,0,0,0}, accR[4] = {0,0,0,0};
        const unsigned long long* xrp = (const unsigned long long*)(sx + node * 128);
        const unsigned long long* xip = (const unsigned long long*)(sx + node * 128 + 64);

        #pragma unroll 8
        for (int d2 = 0; d2 < 32; d2++) {
            unsigned long long x_r = xrp[d2];
            unsigned long long x_i = xip[d2];
            #pragma unroll
            for (int j = 0; j < 4; j++) {
                int o = oq + j * 16;
                unsigned long long wr = *(const unsigned long long*)(sWr + o * WS + 2 * d2);
                unsigned long long wi = *(const unsigned long long*)(sWi + o * WS + 2 * d2);
                ffma2(accA[j], x_r, wr);
                ffma2(accB[j], x_i, wi);
                ffma2(accQ[j], x_i, wr);
                ffma2(accR[j], x_r, wi);
            }
        }

        #pragma unroll
        for (int j = 0; j < 4; j++) {
            float2 fa = unpack2(accA[j]);
            float2 fb = unpack2(accB[j]);
            float2 fq = unpack2(accQ[j]);
            float2 fr = unpack2(accR[j]);
            float a = fa.x + fa.y, b = fb.x + fb.y;
            float q = fq.x + fq.y, r = fr.x + fr.y;
            int o = oq + j * 16;
            size_t gi = (size_t)(nbase + node) * DF + o;
            g_U [gi] = 0.5f * (a - b);
            g_Vt[gi] = 0.5f * q;
            g_Vf[gi] = r + 0.5f * q;
        }
        __syncthreads();  // protect sx before next tile's restage
    }
}

__global__ void k_init_out(float* __restrict__ out) {
    int i = blockIdx.x * blockDim.x + threadIdx.x;
    if (i < NN * DF) {
        int o = i & 63;
        out[i]           = g_breal[o];
        out[NN * DF + i] = g_bimag[o];
    }
}

// Main edge pass: one warp per edge.
//   forward  (scatter row, gather col): out_r[row] += w*U[col];  out_i[row] += w*Vf[col]
//   transpose(scatter col, gather row): out_r[col] += w*U[row];  out_i[col] += w*Vt[row]
// Half-warp 0 handles forward, half-warp 1 handles transpose; per-lane f = k*16 + j
// keeps every LDG / RED instruction 64B-contiguous per half-warp.
__global__ __launch_bounds__(256) void k_edge(const int* __restrict__ ei,
                                              float* __restrict__ out) {
    int gwarp = (blockIdx.x * 256 + threadIdx.x) >> 5;
    int lane  = threadIdx.x & 31;
    int nw    = (gridDim.x * 256) >> 5;
    int j     = lane & 15;
    int half  = lane >> 4;
    float* outi = out + NN * DF;

    for (int e = gwarp; e < NE; e += nw) {
        int row = __ldg(ei + e);
        int col = __ldg(ei + NE + e);
        float w = g_outinv[row] * g_ininv[col];

        int gbase = (half ? row : col) * DF;  // gather node
        int sbase = (half ? col : row) * DF;  // scatter node
        const float* B = half ? g_Vt : g_Vf;

        #pragma unroll
        for (int k = 0; k < 4; k++) {
            int f = k * 16 + j;
            atomicAdd(out  + sbase + f, w * __ldg(g_U + gbase + f));
            atomicAdd(outi + sbase + f, w * __ldg(B   + gbase + f));
        }
    }
}

// ---------------- launch ----------------
extern "C" void kernel_launch(void* const* d_in, const int* in_sizes, int n_in,
                              void* d_out, int out_size) {
    const float* xr = (const float*)d_in[0];
    const float* xi = (const float*)d_in[1];
    const int*   ei = (const int*)  d_in[2];
    const float* Wr = (const float*)d_in[3];
    const float* br = (const float*)d_in[4];
    const float* Wi = (const float*)d_in[5];
    const float* bi = (const float*)d_in[6];
    float* out = (float*)d_out;

    k_zero_deg<<<(NN + 255) / 256, 256>>>();
    k_deg<<<(NE + 255) / 256, 256>>>(ei);
    k_inv<<<(NN + 255) / 256, 256>>>();
    k_weights<<<16, 256>>>(Wr, br, Wi, bi);
    k_transform<<<592, 256>>>(xr, xi);
    k_init_out<<<(NN * DF + 255) / 256, 256>>>(out);
    k_edge<<<2368, 256>>>(ei, out);
}